// round 1
// baseline (speedup 1.0000x reference)
#include <cuda_runtime.h>
#include <cuda_bf16.h>
#include <math.h>

#define NB 16
#define ND 256
#define NL 256
#define NT 1000
#define NCH 8
#define NDW 4
#define NDC 2

// ---------------- scratch (device globals; no allocations allowed) ----------
__device__ __align__(16) float g_sd[NB * NL];
__device__ __align__(16) float g_sk[NB * NL];
__device__ int g_flen[NB];
__device__ __align__(16) float g_weff[ND * 48];       // [d][br*8+ch][k]
__device__ __align__(16) float g_cwpb[48];            // [br][ch][k]
__device__ __align__(16) float g_h[2][NB * NL * NCH]; // [branch][(b*L+l)*8+ch]
__device__ __align__(16) float g_M[(size_t)NB * 1024 * 256];   // [b][l*4+q][o]
__device__ __align__(16) float g_w[(size_t)NB * NT * 1024];    // [b][t][l*4+q]
__device__ __align__(16) float g_wc8[(size_t)NB * NT * 8];     // [b][t][q*2+p]

__device__ __forceinline__ float swishf(float z) {
    return z / (1.0f + expf(-z));
}

// ---------------- K1: cumsum scan, frame_len ------------------------------
__global__ void k_scan(const float* __restrict__ dur) {
    int b = blockIdx.x, l = threadIdx.x;
    __shared__ float s[NL];
    float x = dur[b * NL + l];
    s[l] = x;
    __syncthreads();
#pragma unroll
    for (int off = 1; off < NL; off <<= 1) {
        float v = (l >= off) ? s[l - off] : 0.0f;
        __syncthreads();
        s[l] += v;
        __syncthreads();
    }
    float sd = s[l];
    g_sd[b * NL + l] = sd;
    g_sk[b * NL + l] = sd - x;
    if (l == 0) {
        float tot = s[NL - 1];
        int fl = (int)rintf(tot);
        if (fl < 0) fl = 0;
        if (fl > NT) fl = NT;
        g_flen[b] = fl;
    }
}

// ---------------- K2: fold projection into conv weights -------------------
__global__ void k_weff(const float* __restrict__ pwW, const float* __restrict__ cwW,
                       const float* __restrict__ pcW, const float* __restrict__ ccW) {
    int k = blockIdx.x, ch = blockIdx.y, br = blockIdx.z, d = threadIdx.x;
    const float* cw = br ? ccW : cwW;
    const float* pw = br ? pcW : pwW;
    float acc = 0.0f;
#pragma unroll 4
    for (int o = 0; o < ND; o++)
        acc += cw[(ch * ND + o) * 3 + k] * pw[o * ND + d];
    g_weff[d * 48 + (br * 8 + ch) * 3 + k] = acc;
}

__global__ void k_cwpb(const float* __restrict__ cwW, const float* __restrict__ pwb,
                       const float* __restrict__ ccW, const float* __restrict__ pcb) {
    int i = threadIdx.x;
    if (i >= 48) return;
    int br = i / 24, rem = i % 24, ch = rem / 3, k = rem % 3;
    const float* cw = br ? ccW : cwW;
    const float* pb = br ? pcb : pwb;
    float a = 0.0f;
    for (int o = 0; o < ND; o++) a += cw[(ch * ND + o) * 3 + k] * pb[o];
    g_cwpb[i] = a;
}

// ---------------- K3: fused proj+conv+swish+mask for both branches --------
__global__ void k_conv(const float* __restrict__ ph, const float* __restrict__ dur,
                       const float* __restrict__ cwb, const float* __restrict__ ccb) {
    __shared__ __align__(16) float sWe[ND * 48];
    int b = blockIdx.x, l = threadIdx.x;
    for (int i = l; i < ND * 48 / 4; i += NL)
        ((float4*)sWe)[i] = ((const float4*)g_weff)[i];
    __syncthreads();

    const float* phb = ph + (size_t)b * ND * NL;
    float acc[16];
#pragma unroll
    for (int i = 0; i < 16; i++) acc[i] = 0.0f;

    for (int d = 0; d < ND; d++) {
        float vm = (l > 0) ? phb[d * NL + l - 1] : 0.0f;
        float v0 = phb[d * NL + l];
        float vp = (l < NL - 1) ? phb[d * NL + l + 1] : 0.0f;
        float v[3] = {vm, v0, vp};
        const float* wd = sWe + d * 48;
#pragma unroll
        for (int lin = 0; lin < 48; lin += 4) {
            float4 w = *(const float4*)(wd + lin);
            acc[(lin + 0) / 3] += w.x * v[(lin + 0) % 3];
            acc[(lin + 1) / 3] += w.y * v[(lin + 1) % 3];
            acc[(lin + 2) / 3] += w.z * v[(lin + 2) % 3];
            acc[(lin + 3) / 3] += w.w * v[(lin + 3) % 3];
        }
    }
    bool pad = (dur[b * NL + l] == 0.0f);
#pragma unroll
    for (int idx = 0; idx < 16; idx++) {
        int br = idx >> 3, ch = idx & 7;
        float bias = (br ? ccb : cwb)[ch];
        float c0 = g_cwpb[br * 24 + ch * 3 + 0];
        float c1 = g_cwpb[br * 24 + ch * 3 + 1];
        float c2 = g_cwpb[br * 24 + ch * 3 + 2];
        bias += c0 + c1 + c2;
        if (l == 0) bias -= c0;
        if (l == NL - 1) bias -= c2;
        float z = acc[idx] + bias;
        float h = pad ? 0.0f : swishf(z);
        g_h[br][(b * NL + l) * NCH + ch] = h;
    }
}

// ---------------- K4: M[b,l,q,o] = sum_h ph[b,h,l] * lin_w_W[q*D+h,o] -----
__global__ void k_mgemm(const float* __restrict__ ph, const float* __restrict__ linw) {
    int bq = blockIdx.z;
    int b = bq >> 2, q = bq & 3;
    int l0 = blockIdx.y * 64, n0 = blockIdx.x * 64;
    __shared__ __align__(16) float As[16][68];
    __shared__ __align__(16) float Bs[16][68];
    int tid = threadIdx.x;
    int ty = tid >> 4, tx = tid & 15;
    float acc[4][4];
#pragma unroll
    for (int i = 0; i < 4; i++)
#pragma unroll
        for (int j = 0; j < 4; j++) acc[i][j] = 0.0f;

    const float* Ab = ph + (size_t)b * ND * NL;            // A[l,h] = Ab[h*L + l]
    const float* Bb = linw + (size_t)q * ND * 256;         // B[h,o]

    for (int k0 = 0; k0 < ND; k0 += 16) {
        float4 av = *(const float4*)(Ab + (size_t)(k0 + ty) * NL + l0 + tx * 4);
        *(float4*)(&As[ty][tx * 4]) = av;
        float4 bv = *(const float4*)(Bb + (size_t)(k0 + ty) * 256 + n0 + tx * 4);
        *(float4*)(&Bs[ty][tx * 4]) = bv;
        __syncthreads();
#pragma unroll
        for (int k = 0; k < 16; k++) {
            float4 a = *(const float4*)(&As[k][ty * 4]);
            float4 bb = *(const float4*)(&Bs[k][tx * 4]);
            float aa[4] = {a.x, a.y, a.z, a.w};
            float bbv[4] = {bb.x, bb.y, bb.z, bb.w};
#pragma unroll
            for (int i = 0; i < 4; i++)
#pragma unroll
                for (int j = 0; j < 4; j++) acc[i][j] += aa[i] * bbv[j];
        }
        __syncthreads();
    }
#pragma unroll
    for (int im = 0; im < 4; im++) {
        int l = l0 + ty * 4 + im;
        int row = l * 4 + q;
        float4 o = make_float4(acc[im][0], acc[im][1], acc[im][2], acc[im][3]);
        *(float4*)(g_M + ((size_t)b * 1024 + row) * 256 + n0 + tx * 4) = o;
    }
}

// ---------------- K5: w (softmax over L) + c + wc8 per (b,t) --------------
__global__ void k_wsm(const float* __restrict__ dur,
                      const float* __restrict__ mwW, const float* __restrict__ mwb,
                      const float* __restrict__ mcW, const float* __restrict__ mcb) {
    int t = blockIdx.x, b = blockIdx.y, l = threadIdx.x;
    float* wout = g_w + ((size_t)(b * NT + t)) * 1024;
    if (t >= g_flen[b]) {
        *(float4*)(wout + l * 4) = make_float4(0, 0, 0, 0);
        if (l < 8) g_wc8[((size_t)(b * NT + t)) * 8 + l] = 0.0f;
        return;
    }
    __shared__ float smw[40], smwb4[4], smc[20], smcb2[2];
    __shared__ float red[8][4];
    __shared__ float red8[8][8];
    if (l < 40) smw[l] = mwW[l];
    if (l < 4) smwb4[l] = mwb[l];
    if (l >= 64 && l < 84) smc[l - 64] = mcW[l - 64];
    if (l >= 96 && l < 98) smcb2[l - 96] = mcb[l - 96];

    float du = dur[b * NL + l];
    bool pad = (du == 0.0f);
    float skv = g_sk[b * NL + l];
    float sdv = g_sd[b * NL + l];
    float4 hw0 = *(const float4*)(&g_h[0][(b * NL + l) * 8]);
    float4 hw1 = *(const float4*)(&g_h[0][(b * NL + l) * 8 + 4]);
    float4 hc0 = *(const float4*)(&g_h[1][(b * NL + l) * 8]);
    float4 hc1 = *(const float4*)(&g_h[1][(b * NL + l) * 8 + 4]);
    __syncthreads();

    float S = pad ? 0.0f : ((float)(t + 1) - skv);
    float E = pad ? 0.0f : (sdv - skv);
    float hwv[8] = {hw0.x, hw0.y, hw0.z, hw0.w, hw1.x, hw1.y, hw1.z, hw1.w};
    float hcv[8] = {hc0.x, hc0.y, hc0.z, hc0.w, hc1.x, hc1.y, hc1.z, hc1.w};

    float lg[4];
#pragma unroll
    for (int q = 0; q < 4; q++) {
        float z = smwb4[q] + S * smw[q] + E * smw[4 + q];
#pragma unroll
        for (int ch = 0; ch < 8; ch++) z += hwv[ch] * smw[(2 + ch) * 4 + q];
        float pre = swishf(z);
        lg[q] = pad ? -1e30f : pre;
    }

    const unsigned FULL = 0xffffffffu;
    int wid = l >> 5, lane = l & 31;
    // --- block max ---
    float4 v = make_float4(lg[0], lg[1], lg[2], lg[3]);
#pragma unroll
    for (int off = 16; off > 0; off >>= 1) {
        v.x = fmaxf(v.x, __shfl_down_sync(FULL, v.x, off));
        v.y = fmaxf(v.y, __shfl_down_sync(FULL, v.y, off));
        v.z = fmaxf(v.z, __shfl_down_sync(FULL, v.z, off));
        v.w = fmaxf(v.w, __shfl_down_sync(FULL, v.w, off));
    }
    if (lane == 0) { red[wid][0] = v.x; red[wid][1] = v.y; red[wid][2] = v.z; red[wid][3] = v.w; }
    __syncthreads();
    float mx[4] = {-1e30f, -1e30f, -1e30f, -1e30f};
#pragma unroll
    for (int w = 0; w < 8; w++)
#pragma unroll
        for (int q = 0; q < 4; q++) mx[q] = fmaxf(mx[q], red[w][q]);
    __syncthreads();

    float e[4];
#pragma unroll
    for (int q = 0; q < 4; q++) e[q] = pad ? 0.0f : expf(lg[q] - mx[q]);

    // --- block sum ---
    float4 sv = make_float4(e[0], e[1], e[2], e[3]);
#pragma unroll
    for (int off = 16; off > 0; off >>= 1) {
        sv.x += __shfl_down_sync(FULL, sv.x, off);
        sv.y += __shfl_down_sync(FULL, sv.y, off);
        sv.z += __shfl_down_sync(FULL, sv.z, off);
        sv.w += __shfl_down_sync(FULL, sv.w, off);
    }
    if (lane == 0) { red[wid][0] = sv.x; red[wid][1] = sv.y; red[wid][2] = sv.z; red[wid][3] = sv.w; }
    __syncthreads();
    float sm[4] = {0, 0, 0, 0};
#pragma unroll
    for (int w = 0; w < 8; w++)
#pragma unroll
        for (int q = 0; q < 4; q++) sm[q] += red[w][q];

    float wq[4];
#pragma unroll
    for (int q = 0; q < 4; q++) wq[q] = e[q] / sm[q];
    *(float4*)(wout + l * 4) = make_float4(wq[0], wq[1], wq[2], wq[3]);

    // --- c ---
    float cp[2];
#pragma unroll
    for (int p = 0; p < 2; p++) {
        float z = smcb2[p] + S * smc[p] + E * smc[2 + p];
#pragma unroll
        for (int ch = 0; ch < 8; ch++) z += hcv[ch] * smc[(2 + ch) * 2 + p];
        cp[p] = swishf(z);
    }
    float prod[8];
#pragma unroll
    for (int q = 0; q < 4; q++)
#pragma unroll
        for (int p = 0; p < 2; p++) prod[q * 2 + p] = wq[q] * cp[p];
#pragma unroll
    for (int off = 16; off > 0; off >>= 1)
#pragma unroll
        for (int j = 0; j < 8; j++) prod[j] += __shfl_down_sync(FULL, prod[j], off);
    if (lane == 0)
#pragma unroll
        for (int j = 0; j < 8; j++) red8[wid][j] = prod[j];
    __syncthreads();
    if (l < 8) {
        float s = 0.0f;
#pragma unroll
        for (int w = 0; w < 8; w++) s += red8[w][l];
        g_wc8[((size_t)(b * NT + t)) * 8 + l] = s;
    }
}

// ---------------- K6: out = w @ M + (wc8 @ lin_c_W) + biases --------------
__global__ void k_final(const float* __restrict__ lwb, const float* __restrict__ lcW,
                        const float* __restrict__ lcb, float* __restrict__ out) {
    int b = blockIdx.z;
    int t0 = blockIdx.y * 128;
    int n0 = blockIdx.x * 64;
    __shared__ __align__(16) float As[16][132];
    __shared__ __align__(16) float Bs[16][68];
    __shared__ float sB[64];
    __shared__ float sC[8][64];
    int tid = threadIdx.x;
    int ty = tid >> 4, tx = tid & 15;

    if (tid < 64) sB[tid] = lwb[n0 + tid] + lcb[n0 + tid];
    for (int i = tid; i < 512; i += 256)
        sC[i >> 6][i & 63] = lcW[(i >> 6) * 256 + n0 + (i & 63)];

    const float* Ab = g_w + (size_t)b * NT * 1024;
    const float* Bb = g_M + (size_t)b * 1024 * 256;
    float acc[8][4];
#pragma unroll
    for (int i = 0; i < 8; i++)
#pragma unroll
        for (int j = 0; j < 4; j++) acc[i][j] = 0.0f;

    for (int k0 = 0; k0 < 1024; k0 += 16) {
#pragma unroll
        for (int p = 0; p < 2; p++) {
            int r = p * 64 + (tid >> 2);
            int c4 = (tid & 3) * 4;
            float4 av = (t0 + r < NT)
                ? *(const float4*)(Ab + (size_t)(t0 + r) * 1024 + k0 + c4)
                : make_float4(0, 0, 0, 0);
            As[c4 + 0][r] = av.x;
            As[c4 + 1][r] = av.y;
            As[c4 + 2][r] = av.z;
            As[c4 + 3][r] = av.w;
        }
        float4 bv = *(const float4*)(Bb + (size_t)(k0 + ty) * 256 + n0 + tx * 4);
        *(float4*)(&Bs[ty][tx * 4]) = bv;
        __syncthreads();
#pragma unroll
        for (int k = 0; k < 16; k++) {
            float4 a0 = *(const float4*)(&As[k][ty * 8]);
            float4 a1 = *(const float4*)(&As[k][ty * 8 + 4]);
            float4 bb = *(const float4*)(&Bs[k][tx * 4]);
            float aa[8] = {a0.x, a0.y, a0.z, a0.w, a1.x, a1.y, a1.z, a1.w};
            float bbv[4] = {bb.x, bb.y, bb.z, bb.w};
#pragma unroll
            for (int i = 0; i < 8; i++)
#pragma unroll
                for (int j = 0; j < 4; j++) acc[i][j] += aa[i] * bbv[j];
        }
        __syncthreads();
    }

#pragma unroll
    for (int im = 0; im < 8; im++) {
        int t = t0 + ty * 8 + im;
        if (t < NT) {
            const float* wc = g_wc8 + ((size_t)(b * NT + t)) * 8;
            float wcr[8];
#pragma unroll
            for (int j = 0; j < 8; j++) wcr[j] = wc[j];
            float ov[4];
#pragma unroll
            for (int u = 0; u < 4; u++) {
                int nl = tx * 4 + u;
                float vv = acc[im][u] + sB[nl];
#pragma unroll
                for (int j = 0; j < 8; j++) vv += wcr[j] * sC[j][nl];
                ov[u] = vv;
            }
            *(float4*)(out + ((size_t)(b * NT + t)) * 256 + n0 + tx * 4) =
                make_float4(ov[0], ov[1], ov[2], ov[3]);
        }
    }
}

// ---------------------------------------------------------------------------
extern "C" void kernel_launch(void* const* d_in, const int* in_sizes, int n_in,
                              void* d_out, int out_size) {
    const float* durations = (const float*)d_in[0];
    const float* phoneme   = (const float*)d_in[1];
    // d_in[2] = phoneme_mask (unused; derived from durations == 0)
    const float* proj_w_W  = (const float*)d_in[3];
    const float* proj_w_b  = (const float*)d_in[4];
    const float* conv_w_W  = (const float*)d_in[5];
    const float* conv_w_b  = (const float*)d_in[6];
    const float* mlp_w_W   = (const float*)d_in[7];
    const float* mlp_w_b   = (const float*)d_in[8];
    const float* lin_w_W   = (const float*)d_in[9];
    const float* lin_w_b   = (const float*)d_in[10];
    const float* proj_c_W  = (const float*)d_in[11];
    const float* proj_c_b  = (const float*)d_in[12];
    const float* conv_c_W  = (const float*)d_in[13];
    const float* conv_c_b  = (const float*)d_in[14];
    const float* mlp_c_W   = (const float*)d_in[15];
    const float* mlp_c_b   = (const float*)d_in[16];
    const float* lin_c_W   = (const float*)d_in[17];
    const float* lin_c_b   = (const float*)d_in[18];
    float* out = (float*)d_out;

    k_scan<<<NB, NL>>>(durations);
    k_weff<<<dim3(3, 8, 2), ND>>>(proj_w_W, conv_w_W, proj_c_W, conv_c_W);
    k_cwpb<<<1, 64>>>(conv_w_W, proj_w_b, conv_c_W, proj_c_b);
    k_conv<<<NB, NL>>>(phoneme, durations, conv_w_b, conv_c_b);
    k_mgemm<<<dim3(4, 4, NB * NDW), 256>>>(phoneme, lin_w_W);
    k_wsm<<<dim3(NT, NB), NL>>>(durations, mlp_w_W, mlp_w_b, mlp_c_W, mlp_c_b);
    k_final<<<dim3(4, 8, NB), 256>>>(lin_w_b, lin_c_W, lin_c_b, out);
}

// round 4
// speedup vs baseline: 1.8825x; 1.8825x over previous
#include <cuda_runtime.h>
#include <cuda_bf16.h>
#include <math.h>
#include <stdint.h>

#define NB 16
#define ND 256
#define NL 256
#define NT 1000
#define NCH 8
#define NDW 4
#define NDC 2

// ---------------- scratch (device globals; no allocations allowed) ----------
__device__ __align__(16) float g_sd[NB * NL];
__device__ __align__(16) float g_sk[NB * NL];
__device__ int g_flen[NB];
__device__ __align__(16) float g_weff[ND * 48];       // [d][br*8+ch][k]
__device__ __align__(16) float g_cwpb[48];            // [br][ch][k]
__device__ __align__(16) float g_hpart[16 * NB * NL * 16]; // [chunk][(b*L+l)*16+idx]
__device__ __align__(16) float g_h[2][NB * NL * NCH]; // [branch][(b*L+l)*8+ch]
__device__ __align__(16) float g_M[(size_t)NB * 1024 * 256];   // [b][l*4+q][o]  (tf32-rounded)
__device__ __align__(16) float g_w[(size_t)NB * NT * 1024];    // [b][t][l*4+q]  (tf32-rounded)
__device__ __align__(16) float g_wc8[(size_t)NB * NT * 8];     // [b][t][q*2+p]

__device__ __forceinline__ float swishf(float z) {
    return z / (1.0f + expf(-z));
}
__device__ __forceinline__ float to_tf32(float x) {
    uint32_t u;
    asm("cvt.rna.tf32.f32 %0, %1;" : "=r"(u) : "f"(x));
    return __uint_as_float(u);
}
__device__ __forceinline__ void mma_tf32(float c[4], uint32_t a0, uint32_t a1,
                                         uint32_t a2, uint32_t a3,
                                         uint32_t b0, uint32_t b1) {
    asm volatile(
        "mma.sync.aligned.m16n8k8.row.col.f32.tf32.tf32.f32 "
        "{%0,%1,%2,%3}, {%4,%5,%6,%7}, {%8,%9}, {%0,%1,%2,%3};\n"
        : "+f"(c[0]), "+f"(c[1]), "+f"(c[2]), "+f"(c[3])
        : "r"(a0), "r"(a1), "r"(a2), "r"(a3), "r"(b0), "r"(b1));
}

// ---------------- K1: cumsum scan, frame_len ------------------------------
__global__ void k_scan(const float* __restrict__ dur) {
    int b = blockIdx.x, l = threadIdx.x;
    __shared__ float s[NL];
    float x = dur[b * NL + l];
    s[l] = x;
    __syncthreads();
#pragma unroll
    for (int off = 1; off < NL; off <<= 1) {
        float v = (l >= off) ? s[l - off] : 0.0f;
        __syncthreads();
        s[l] += v;
        __syncthreads();
    }
    float sd = s[l];
    g_sd[b * NL + l] = sd;
    g_sk[b * NL + l] = sd - x;
    if (l == 0) {
        float tot = s[NL - 1];
        int fl = (int)rintf(tot);
        if (fl < 0) fl = 0;
        if (fl > NT) fl = NT;
        g_flen[b] = fl;
    }
}

// ---------------- K2: fold projection into conv weights -------------------
__global__ void k_weff(const float* __restrict__ pwW, const float* __restrict__ cwW,
                       const float* __restrict__ pcW, const float* __restrict__ ccW) {
    int k = blockIdx.x, ch = blockIdx.y, br = blockIdx.z, d = threadIdx.x;
    const float* cw = br ? ccW : cwW;
    const float* pw = br ? pcW : pwW;
    float acc = 0.0f;
#pragma unroll 4
    for (int o = 0; o < ND; o++)
        acc += cw[(ch * ND + o) * 3 + k] * pw[o * ND + d];
    g_weff[d * 48 + (br * 8 + ch) * 3 + k] = acc;
}

__global__ void k_cwpb(const float* __restrict__ cwW, const float* __restrict__ pwb,
                       const float* __restrict__ ccW, const float* __restrict__ pcb) {
    int i = threadIdx.x;
    if (i >= 48) return;
    int br = i / 24, rem = i % 24, ch = rem / 3, k = rem % 3;
    const float* cw = br ? ccW : cwW;
    const float* pb = br ? pcb : pwb;
    float a = 0.0f;
    for (int o = 0; o < ND; o++) a += cw[(ch * ND + o) * 3 + k] * pb[o];
    g_cwpb[i] = a;
}

// ---------------- K3a: partial conv over 16-d chunks ----------------------
__global__ void k_conv_part(const float* __restrict__ ph) {
    int b = blockIdx.x, c = blockIdx.y, l = threadIdx.x;
    __shared__ __align__(16) float sWe[16 * 48];
    for (int i = l; i < 16 * 48; i += NL) sWe[i] = g_weff[c * 16 * 48 + i];
    __syncthreads();

    const float* phb = ph + (size_t)b * ND * NL + (size_t)(c * 16) * NL;
    float acc[16];
#pragma unroll
    for (int i = 0; i < 16; i++) acc[i] = 0.0f;

#pragma unroll
    for (int dd = 0; dd < 16; dd++) {
        float vm = (l > 0) ? phb[dd * NL + l - 1] : 0.0f;
        float v0 = phb[dd * NL + l];
        float vp = (l < NL - 1) ? phb[dd * NL + l + 1] : 0.0f;
        float v[3] = {vm, v0, vp};
        const float* wd = sWe + dd * 48;
#pragma unroll
        for (int lin = 0; lin < 48; lin += 4) {
            float4 w = *(const float4*)(wd + lin);
            acc[(lin + 0) / 3] += w.x * v[(lin + 0) % 3];
            acc[(lin + 1) / 3] += w.y * v[(lin + 1) % 3];
            acc[(lin + 2) / 3] += w.z * v[(lin + 2) % 3];
            acc[(lin + 3) / 3] += w.w * v[(lin + 3) % 3];
        }
    }
    float* outp = g_hpart + ((size_t)(c * NB + b) * NL + l) * 16;
#pragma unroll
    for (int i = 0; i < 16; i += 4)
        *(float4*)(outp + i) = make_float4(acc[i], acc[i + 1], acc[i + 2], acc[i + 3]);
}

// ---------------- K3b: reduce partials + bias + swish + mask --------------
__global__ void k_conv_fin(const float* __restrict__ dur,
                           const float* __restrict__ cwb, const float* __restrict__ ccb) {
    int b = blockIdx.x, l = threadIdx.x;
    float acc[16];
#pragma unroll
    for (int i = 0; i < 16; i++) acc[i] = 0.0f;
#pragma unroll
    for (int c = 0; c < 16; c++) {
        const float* p = g_hpart + ((size_t)(c * NB + b) * NL + l) * 16;
#pragma unroll
        for (int i = 0; i < 16; i += 4) {
            float4 v = *(const float4*)(p + i);
            acc[i] += v.x; acc[i + 1] += v.y; acc[i + 2] += v.z; acc[i + 3] += v.w;
        }
    }
    bool pad = (dur[b * NL + l] == 0.0f);
#pragma unroll
    for (int idx = 0; idx < 16; idx++) {
        int br = idx >> 3, ch = idx & 7;
        float bias = (br ? ccb : cwb)[ch];
        float c0 = g_cwpb[br * 24 + ch * 3 + 0];
        float c1 = g_cwpb[br * 24 + ch * 3 + 1];
        float c2 = g_cwpb[br * 24 + ch * 3 + 2];
        bias += c0 + c1 + c2;
        if (l == 0) bias -= c0;
        if (l == NL - 1) bias -= c2;
        float z = acc[idx] + bias;
        float h = pad ? 0.0f : swishf(z);
        g_h[br][(b * NL + l) * NCH + ch] = h;
    }
}

// ---------------- K4: M[b,l,q,o] = sum_h ph[b,h,l] * lin_w_W[q*D+h,o] -----
__global__ void k_mgemm(const float* __restrict__ ph, const float* __restrict__ linw) {
    int bq = blockIdx.z;
    int b = bq >> 2, q = bq & 3;
    int l0 = blockIdx.y * 64, n0 = blockIdx.x * 64;
    __shared__ __align__(16) float As[16][68];
    __shared__ __align__(16) float Bs[16][68];
    int tid = threadIdx.x;
    int ty = tid >> 4, tx = tid & 15;
    float acc[4][4];
#pragma unroll
    for (int i = 0; i < 4; i++)
#pragma unroll
        for (int j = 0; j < 4; j++) acc[i][j] = 0.0f;

    const float* Ab = ph + (size_t)b * ND * NL;            // A[l,h] = Ab[h*L + l]
    const float* Bb = linw + (size_t)q * ND * 256;         // B[h,o]

    for (int k0 = 0; k0 < ND; k0 += 16) {
        float4 av = *(const float4*)(Ab + (size_t)(k0 + ty) * NL + l0 + tx * 4);
        *(float4*)(&As[ty][tx * 4]) = av;
        float4 bv = *(const float4*)(Bb + (size_t)(k0 + ty) * 256 + n0 + tx * 4);
        *(float4*)(&Bs[ty][tx * 4]) = bv;
        __syncthreads();
#pragma unroll
        for (int k = 0; k < 16; k++) {
            float4 a = *(const float4*)(&As[k][ty * 4]);
            float4 bb = *(const float4*)(&Bs[k][tx * 4]);
            float aa[4] = {a.x, a.y, a.z, a.w};
            float bbv[4] = {bb.x, bb.y, bb.z, bb.w};
#pragma unroll
            for (int i = 0; i < 4; i++)
#pragma unroll
                for (int j = 0; j < 4; j++) acc[i][j] += aa[i] * bbv[j];
        }
        __syncthreads();
    }
#pragma unroll
    for (int im = 0; im < 4; im++) {
        int l = l0 + ty * 4 + im;
        int row = l * 4 + q;
        float4 o = make_float4(to_tf32(acc[im][0]), to_tf32(acc[im][1]),
                               to_tf32(acc[im][2]), to_tf32(acc[im][3]));
        *(float4*)(g_M + ((size_t)b * 1024 + row) * 256 + n0 + tx * 4) = o;
    }
}

// ---------------- K5: w (softmax over L) + c + wc8 per (b,t) --------------
__global__ void k_wsm(const float* __restrict__ dur,
                      const float* __restrict__ mwW, const float* __restrict__ mwb,
                      const float* __restrict__ mcW, const float* __restrict__ mcb) {
    int t = blockIdx.x, b = blockIdx.y, l = threadIdx.x;
    float* wout = g_w + ((size_t)(b * NT + t)) * 1024;
    if (t >= g_flen[b]) {
        *(float4*)(wout + l * 4) = make_float4(0, 0, 0, 0);
        if (l < 8) g_wc8[((size_t)(b * NT + t)) * 8 + l] = 0.0f;
        return;
    }
    __shared__ float smw[40], smwb4[4], smc[20], smcb2[2];
    __shared__ float red[8][4];
    __shared__ float red8[8][8];
    if (l < 40) smw[l] = mwW[l];
    if (l < 4) smwb4[l] = mwb[l];
    if (l >= 64 && l < 84) smc[l - 64] = mcW[l - 64];
    if (l >= 96 && l < 98) smcb2[l - 96] = mcb[l - 96];

    float du = dur[b * NL + l];
    bool pad = (du == 0.0f);
    float skv = g_sk[b * NL + l];
    float sdv = g_sd[b * NL + l];
    float4 hw0 = *(const float4*)(&g_h[0][(b * NL + l) * 8]);
    float4 hw1 = *(const float4*)(&g_h[0][(b * NL + l) * 8 + 4]);
    float4 hc0 = *(const float4*)(&g_h[1][(b * NL + l) * 8]);
    float4 hc1 = *(const float4*)(&g_h[1][(b * NL + l) * 8 + 4]);
    __syncthreads();

    float S = pad ? 0.0f : ((float)(t + 1) - skv);
    float E = pad ? 0.0f : (sdv - skv);
    float hwv[8] = {hw0.x, hw0.y, hw0.z, hw0.w, hw1.x, hw1.y, hw1.z, hw1.w};
    float hcv[8] = {hc0.x, hc0.y, hc0.z, hc0.w, hc1.x, hc1.y, hc1.z, hc1.w};

    float lg[4];
#pragma unroll
    for (int q = 0; q < 4; q++) {
        float z = smwb4[q] + S * smw[q] + E * smw[4 + q];
#pragma unroll
        for (int ch = 0; ch < 8; ch++) z += hwv[ch] * smw[(2 + ch) * 4 + q];
        float pre = swishf(z);
        lg[q] = pad ? -1e30f : pre;
    }

    const unsigned FULL = 0xffffffffu;
    int wid = l >> 5, lane = l & 31;
    float4 v = make_float4(lg[0], lg[1], lg[2], lg[3]);
#pragma unroll
    for (int off = 16; off > 0; off >>= 1) {
        v.x = fmaxf(v.x, __shfl_down_sync(FULL, v.x, off));
        v.y = fmaxf(v.y, __shfl_down_sync(FULL, v.y, off));
        v.z = fmaxf(v.z, __shfl_down_sync(FULL, v.z, off));
        v.w = fmaxf(v.w, __shfl_down_sync(FULL, v.w, off));
    }
    if (lane == 0) { red[wid][0] = v.x; red[wid][1] = v.y; red[wid][2] = v.z; red[wid][3] = v.w; }
    __syncthreads();
    float mx[4] = {-1e30f, -1e30f, -1e30f, -1e30f};
#pragma unroll
    for (int w = 0; w < 8; w++)
#pragma unroll
        for (int q = 0; q < 4; q++) mx[q] = fmaxf(mx[q], red[w][q]);
    __syncthreads();

    float e[4];
#pragma unroll
    for (int q = 0; q < 4; q++) e[q] = pad ? 0.0f : expf(lg[q] - mx[q]);

    float4 sv = make_float4(e[0], e[1], e[2], e[3]);
#pragma unroll
    for (int off = 16; off > 0; off >>= 1) {
        sv.x += __shfl_down_sync(FULL, sv.x, off);
        sv.y += __shfl_down_sync(FULL, sv.y, off);
        sv.z += __shfl_down_sync(FULL, sv.z, off);
        sv.w += __shfl_down_sync(FULL, sv.w, off);
    }
    if (lane == 0) { red[wid][0] = sv.x; red[wid][1] = sv.y; red[wid][2] = sv.z; red[wid][3] = sv.w; }
    __syncthreads();
    float sm[4] = {0, 0, 0, 0};
#pragma unroll
    for (int w = 0; w < 8; w++)
#pragma unroll
        for (int q = 0; q < 4; q++) sm[q] += red[w][q];

    float wq[4];
#pragma unroll
    for (int q = 0; q < 4; q++) wq[q] = e[q] / sm[q];
    *(float4*)(wout + l * 4) = make_float4(to_tf32(wq[0]), to_tf32(wq[1]),
                                           to_tf32(wq[2]), to_tf32(wq[3]));

    float cp[2];
#pragma unroll
    for (int p = 0; p < 2; p++) {
        float z = smcb2[p] + S * smc[p] + E * smc[2 + p];
#pragma unroll
        for (int ch = 0; ch < 8; ch++) z += hcv[ch] * smc[(2 + ch) * 2 + p];
        cp[p] = swishf(z);
    }
    float prod[8];
#pragma unroll
    for (int q = 0; q < 4; q++)
#pragma unroll
        for (int p = 0; p < 2; p++) prod[q * 2 + p] = wq[q] * cp[p];
#pragma unroll
    for (int off = 16; off > 0; off >>= 1)
#pragma unroll
        for (int j = 0; j < 8; j++) prod[j] += __shfl_down_sync(FULL, prod[j], off);
    if (lane == 0)
#pragma unroll
        for (int j = 0; j < 8; j++) red8[wid][j] = prod[j];
    __syncthreads();
    if (l < 8) {
        float s = 0.0f;
#pragma unroll
        for (int w = 0; w < 8; w++) s += red8[w][l];
        g_wc8[((size_t)(b * NT + t)) * 8 + l] = s;
    }
}

// ---------------- K6: out = w @ M (tf32 mma) + (wc8 @ lin_c_W) + biases ---
// block tile 128(t) x 128(n), K-chunk 32, 8 warps (4x2), warp tile 32x64
__global__ __launch_bounds__(256) void k_final(
        const float* __restrict__ lwb, const float* __restrict__ lcW,
        const float* __restrict__ lcb, float* __restrict__ out) {
    int b = blockIdx.z;
    int t0 = blockIdx.y * 128;
    int n0 = blockIdx.x * 128;
    __shared__ __align__(16) float As[128][36];
    __shared__ __align__(16) float Bs[32][136];
    __shared__ float sB[128];
    __shared__ float sC[8][128];
    __shared__ float sWC[128][8];

    int tid = threadIdx.x;
    int wid = tid >> 5, lane = tid & 31;
    int warpRow = wid >> 1, warpCol = wid & 1;
    int g = lane >> 2, tg = lane & 3;

    // epilogue constants
    if (tid < 128) sB[tid] = lwb[n0 + tid] + lcb[n0 + tid];
    for (int i = tid; i < 8 * 128; i += 256)
        sC[i >> 7][i & 127] = lcW[(i >> 7) * 256 + n0 + (i & 127)];
    {
        const float* wcb = g_wc8 + (size_t)b * NT * 8;
#pragma unroll
        for (int i = 0; i < 4; i++) {
            int idx = i * 256 + tid;
            int r = idx >> 3;
            float v = (t0 + r < NT) ? wcb[(size_t)(t0 + r) * 8 + (idx & 7)] : 0.0f;
            sWC[r][idx & 7] = v;
        }
    }

    const float* Ab = g_w + (size_t)b * NT * 1024;
    const float* Bb = g_M + (size_t)b * 1024 * 256;

    float acc[2][8][4];
#pragma unroll
    for (int mt = 0; mt < 2; mt++)
#pragma unroll
        for (int nt = 0; nt < 8; nt++)
#pragma unroll
            for (int j = 0; j < 4; j++) acc[mt][nt][j] = 0.0f;

    for (int k0 = 0; k0 < 1024; k0 += 32) {
        __syncthreads();
        // load A chunk: 128 x 32
#pragma unroll
        for (int i = 0; i < 4; i++) {
            int idx = i * 256 + tid;
            int r = idx >> 3, c4 = (idx & 7) * 4;
            float4 av = (t0 + r < NT)
                ? *(const float4*)(Ab + (size_t)(t0 + r) * 1024 + k0 + c4)
                : make_float4(0, 0, 0, 0);
            *(float4*)(&As[r][c4]) = av;
        }
        // load B chunk: 32 x 128
#pragma unroll
        for (int i = 0; i < 4; i++) {
            int idx = i * 256 + tid;
            int r = idx >> 5, c4 = (idx & 31) * 4;
            float4 bv = *(const float4*)(Bb + (size_t)(k0 + r) * 256 + n0 + c4);
            *(float4*)(&Bs[r][c4]) = bv;
        }
        __syncthreads();
#pragma unroll
        for (int ks = 0; ks < 4; ks++) {
            int k = ks * 8;
            uint32_t af[2][4];
#pragma unroll
            for (int mt = 0; mt < 2; mt++) {
                int r0 = warpRow * 32 + mt * 16 + g;
                af[mt][0] = __float_as_uint(As[r0][k + tg]);
                af[mt][1] = __float_as_uint(As[r0 + 8][k + tg]);
                af[mt][2] = __float_as_uint(As[r0][k + tg + 4]);
                af[mt][3] = __float_as_uint(As[r0 + 8][k + tg + 4]);
            }
#pragma unroll
            for (int nt = 0; nt < 8; nt++) {
                int col = warpCol * 64 + nt * 8 + g;
                uint32_t b0 = __float_as_uint(Bs[k + tg][col]);
                uint32_t b1 = __float_as_uint(Bs[k + tg + 4][col]);
                mma_tf32(acc[0][nt], af[0][0], af[0][1], af[0][2], af[0][3], b0, b1);
                mma_tf32(acc[1][nt], af[1][0], af[1][1], af[1][2], af[1][3], b0, b1);
            }
        }
    }

    // epilogue
#pragma unroll
    for (int mt = 0; mt < 2; mt++) {
        int lr0 = warpRow * 32 + mt * 16 + g;   // local row (c0,c1)
        int lr1 = lr0 + 8;                       // local row (c2,c3)
        float wc0[8], wc1[8];
#pragma unroll
        for (int j = 0; j < 8; j++) { wc0[j] = sWC[lr0][j]; wc1[j] = sWC[lr1][j]; }
        int T0 = t0 + lr0, T1 = t0 + lr1;
#pragma unroll
        for (int nt = 0; nt < 8; nt++) {
            int nl = warpCol * 64 + nt * 8 + 2 * tg;
            float bias0 = sB[nl], bias1 = sB[nl + 1];
            float e00 = acc[mt][nt][0] + bias0, e01 = acc[mt][nt][1] + bias1;
            float e10 = acc[mt][nt][2] + bias0, e11 = acc[mt][nt][3] + bias1;
#pragma unroll
            for (int j = 0; j < 8; j++) {
                float c0v = sC[j][nl], c1v = sC[j][nl + 1];
                e00 += wc0[j] * c0v; e01 += wc0[j] * c1v;
                e10 += wc1[j] * c0v; e11 += wc1[j] * c1v;
            }
            if (T0 < NT)
                *(float2*)(out + ((size_t)(b * NT + T0)) * 256 + n0 + nl) = make_float2(e00, e01);
            if (T1 < NT)
                *(float2*)(out + ((size_t)(b * NT + T1)) * 256 + n0 + nl) = make_float2(e10, e11);
        }
    }
}

// ---------------------------------------------------------------------------
extern "C" void kernel_launch(void* const* d_in, const int* in_sizes, int n_in,
                              void* d_out, int out_size) {
    const float* durations = (const float*)d_in[0];
    const float* phoneme   = (const float*)d_in[1];
    // d_in[2] = phoneme_mask (unused; derived from durations == 0)
    const float* proj_w_W  = (const float*)d_in[3];
    const float* proj_w_b  = (const float*)d_in[4];
    const float* conv_w_W  = (const float*)d_in[5];
    const float* conv_w_b  = (const float*)d_in[6];
    const float* mlp_w_W   = (const float*)d_in[7];
    const float* mlp_w_b   = (const float*)d_in[8];
    const float* lin_w_W   = (const float*)d_in[9];
    const float* lin_w_b   = (const float*)d_in[10];
    const float* proj_c_W  = (const float*)d_in[11];
    const float* proj_c_b  = (const float*)d_in[12];
    const float* conv_c_W  = (const float*)d_in[13];
    const float* conv_c_b  = (const float*)d_in[14];
    const float* mlp_c_W   = (const float*)d_in[15];
    const float* mlp_c_b   = (const float*)d_in[16];
    const float* lin_c_W   = (const float*)d_in[17];
    const float* lin_c_b   = (const float*)d_in[18];
    float* out = (float*)d_out;

    k_scan<<<NB, NL>>>(durations);
    k_weff<<<dim3(3, 8, 2), ND>>>(proj_w_W, conv_w_W, proj_c_W, conv_c_W);
    k_cwpb<<<1, 64>>>(conv_w_W, proj_w_b, conv_c_W, proj_c_b);
    k_conv_part<<<dim3(NB, 16), NL>>>(phoneme);
    k_conv_fin<<<NB, NL>>>(durations, conv_w_b, conv_c_b);
    k_mgemm<<<dim3(4, 4, NB * NDW), 256>>>(phoneme, lin_w_W);
    k_wsm<<<dim3(NT, NB), NL>>>(durations, mlp_w_W, mlp_w_b, mlp_c_W, mlp_c_b);
    k_final<<<dim3(2, 8, NB), 256>>>(lin_w_b, lin_c_W, lin_c_b, out);
}

// round 5
// speedup vs baseline: 2.9302x; 1.5565x over previous
#include <cuda_runtime.h>
#include <cuda_bf16.h>
#include <math.h>
#include <stdint.h>

#define NB 16
#define ND 256
#define NL 256
#define NT 1000
#define NCH 8
#define NDW 4
#define NDC 2

// ---------------- scratch (device globals; no allocations allowed) ----------
__device__ __align__(16) float g_sd[NB * NL];
__device__ __align__(16) float g_sk[NB * NL];
__device__ int g_flen[NB];
__device__ __align__(16) float g_weff[ND * 48];       // [d][br*8+ch][k]
__device__ __align__(16) float g_cwpb[48];            // [br][ch][k]
__device__ __align__(16) float g_hpart[16 * NB * NL * 16]; // [chunk][(b*L+l)*16+idx]
__device__ __align__(16) float g_bzw[NB * NL * 4];    // t-invariant w-logit base
__device__ __align__(16) float g_bzc[NB * NL * 2];    // t-invariant c base
__device__ __align__(16) float g_pad[NB * NL];        // 1.0 if phone_pad
__device__ __align__(16) float g_M[(size_t)NB * 1024 * 256];   // [b][l*4+q][o]  (tf32)
__device__ __align__(16) float g_w[(size_t)NB * NT * 1024];    // [b][t][l*4+q]  (tf32)
__device__ __align__(16) float g_wc8[(size_t)NB * NT * 8];     // [b][t][q*2+p]

__device__ __forceinline__ float swishf(float z) {
    return z / (1.0f + expf(-z));
}
__device__ __forceinline__ float swish_fast(float z) {
    return __fdividef(z, 1.0f + __expf(-z));
}
__device__ __forceinline__ float to_tf32(float x) {
    uint32_t u;
    asm("cvt.rna.tf32.f32 %0, %1;" : "=r"(u) : "f"(x));
    return __uint_as_float(u);
}
__device__ __forceinline__ void mma_tf32(float c[4], uint32_t a0, uint32_t a1,
                                         uint32_t a2, uint32_t a3,
                                         uint32_t b0, uint32_t b1) {
    asm volatile(
        "mma.sync.aligned.m16n8k8.row.col.f32.tf32.tf32.f32 "
        "{%0,%1,%2,%3}, {%4,%5,%6,%7}, {%8,%9}, {%0,%1,%2,%3};\n"
        : "+f"(c[0]), "+f"(c[1]), "+f"(c[2]), "+f"(c[3])
        : "r"(a0), "r"(a1), "r"(a2), "r"(a3), "r"(b0), "r"(b1));
}

// ---------------- K1: cumsum scan, frame_len ------------------------------
__global__ void k_scan(const float* __restrict__ dur) {
    int b = blockIdx.x, l = threadIdx.x;
    __shared__ float s[NL];
    float x = dur[b * NL + l];
    s[l] = x;
    __syncthreads();
#pragma unroll
    for (int off = 1; off < NL; off <<= 1) {
        float v = (l >= off) ? s[l - off] : 0.0f;
        __syncthreads();
        s[l] += v;
        __syncthreads();
    }
    float sd = s[l];
    g_sd[b * NL + l] = sd;
    g_sk[b * NL + l] = sd - x;
    if (l == 0) {
        float tot = s[NL - 1];
        int fl = (int)rintf(tot);
        if (fl < 0) fl = 0;
        if (fl > NT) fl = NT;
        g_flen[b] = fl;
    }
}

// ---------------- K2: fold projection into conv weights -------------------
__global__ void k_weff(const float* __restrict__ pwW, const float* __restrict__ cwW,
                       const float* __restrict__ pcW, const float* __restrict__ ccW) {
    int k = blockIdx.x, ch = blockIdx.y, br = blockIdx.z, d = threadIdx.x;
    const float* cw = br ? ccW : cwW;
    const float* pw = br ? pcW : pwW;
    float acc = 0.0f;
#pragma unroll 4
    for (int o = 0; o < ND; o++)
        acc += cw[(ch * ND + o) * 3 + k] * pw[o * ND + d];
    g_weff[d * 48 + (br * 8 + ch) * 3 + k] = acc;
}

__global__ void k_cwpb(const float* __restrict__ cwW, const float* __restrict__ pwb,
                       const float* __restrict__ ccW, const float* __restrict__ pcb) {
    int i = threadIdx.x;
    if (i >= 48) return;
    int br = i / 24, rem = i % 24, ch = rem / 3, k = rem % 3;
    const float* cw = br ? ccW : cwW;
    const float* pb = br ? pcb : pwb;
    float a = 0.0f;
    for (int o = 0; o < ND; o++) a += cw[(ch * ND + o) * 3 + k] * pb[o];
    g_cwpb[i] = a;
}

// ---------------- K3a: partial conv over 16-d chunks ----------------------
__global__ void k_conv_part(const float* __restrict__ ph) {
    int b = blockIdx.x, c = blockIdx.y, l = threadIdx.x;
    __shared__ __align__(16) float sWe[16 * 48];
    for (int i = l; i < 16 * 48; i += NL) sWe[i] = g_weff[c * 16 * 48 + i];
    __syncthreads();

    const float* phb = ph + (size_t)b * ND * NL + (size_t)(c * 16) * NL;
    float acc[16];
#pragma unroll
    for (int i = 0; i < 16; i++) acc[i] = 0.0f;

#pragma unroll
    for (int dd = 0; dd < 16; dd++) {
        float vm = (l > 0) ? phb[dd * NL + l - 1] : 0.0f;
        float v0 = phb[dd * NL + l];
        float vp = (l < NL - 1) ? phb[dd * NL + l + 1] : 0.0f;
        float v[3] = {vm, v0, vp};
        const float* wd = sWe + dd * 48;
#pragma unroll
        for (int lin = 0; lin < 48; lin += 4) {
            float4 w = *(const float4*)(wd + lin);
            acc[(lin + 0) / 3] += w.x * v[(lin + 0) % 3];
            acc[(lin + 1) / 3] += w.y * v[(lin + 1) % 3];
            acc[(lin + 2) / 3] += w.z * v[(lin + 2) % 3];
            acc[(lin + 3) / 3] += w.w * v[(lin + 3) % 3];
        }
    }
    float* outp = g_hpart + ((size_t)(c * NB + b) * NL + l) * 16;
#pragma unroll
    for (int i = 0; i < 16; i += 4)
        *(float4*)(outp + i) = make_float4(acc[i], acc[i + 1], acc[i + 2], acc[i + 3]);
}

// ---- K3b: reduce partials + bias + swish, then fold h into t-invariant ---
// ---- MLP bases: bzw[l,q], bzc[l,p], pad flag.                          ---
__global__ void k_conv_fin(const float* __restrict__ dur,
                           const float* __restrict__ cwb, const float* __restrict__ ccb,
                           const float* __restrict__ mwW, const float* __restrict__ mwb,
                           const float* __restrict__ mcW, const float* __restrict__ mcb) {
    int b = blockIdx.x, l = threadIdx.x;
    __shared__ float smw[40], smwb[4], smc[20], smcb[2];
    if (l < 40) smw[l] = mwW[l];
    if (l < 4) smwb[l] = mwb[l];
    if (l >= 64 && l < 84) smc[l - 64] = mcW[l - 64];
    if (l >= 96 && l < 98) smcb[l - 96] = mcb[l - 96];

    float acc[16];
#pragma unroll
    for (int i = 0; i < 16; i++) acc[i] = 0.0f;
#pragma unroll
    for (int c = 0; c < 16; c++) {
        const float* p = g_hpart + ((size_t)(c * NB + b) * NL + l) * 16;
#pragma unroll
        for (int i = 0; i < 16; i += 4) {
            float4 v = *(const float4*)(p + i);
            acc[i] += v.x; acc[i + 1] += v.y; acc[i + 2] += v.z; acc[i + 3] += v.w;
        }
    }
    float h[16];
#pragma unroll
    for (int idx = 0; idx < 16; idx++) {
        int br = idx >> 3, ch = idx & 7;
        float bias = (br ? ccb : cwb)[ch];
        float c0 = g_cwpb[br * 24 + ch * 3 + 0];
        float c1 = g_cwpb[br * 24 + ch * 3 + 1];
        float c2 = g_cwpb[br * 24 + ch * 3 + 2];
        bias += c0 + c1 + c2;
        if (l == 0) bias -= c0;
        if (l == NL - 1) bias -= c2;
        h[idx] = swishf(acc[idx] + bias);
    }
    __syncthreads();

    bool pad = (dur[b * NL + l] == 0.0f);
    float skv = g_sk[b * NL + l];
    float sdv = g_sd[b * NL + l];
    float E = pad ? 0.0f : (sdv - skv);
    float oms = pad ? 0.0f : (1.0f - skv);   // (t+1-sk) = t + oms  (pad: S forced 0 path)
    // w branch base: b_q + oms*W0q + E*W1q + sum_ch h*W
    float bzw[4];
#pragma unroll
    for (int q = 0; q < 4; q++) {
        float z = smwb[q] + oms * smw[q] + E * smw[4 + q];
#pragma unroll
        for (int ch = 0; ch < 8; ch++) z += (pad ? 0.0f : h[ch]) * smw[(2 + ch) * 4 + q];
        bzw[q] = z;
    }
    *(float4*)(g_bzw + (b * NL + l) * 4) = make_float4(bzw[0], bzw[1], bzw[2], bzw[3]);
    float bzc[2];
#pragma unroll
    for (int p = 0; p < 2; p++) {
        float z = smcb[p] + oms * smc[p] + E * smc[2 + p];
#pragma unroll
        for (int ch = 0; ch < 8; ch++) z += (pad ? 0.0f : h[8 + ch]) * smc[(2 + ch) * 2 + p];
        bzc[p] = z;
    }
    *(float2*)(g_bzc + (b * NL + l) * 2) = make_float2(bzc[0], bzc[1]);
    g_pad[b * NL + l] = pad ? 1.0f : 0.0f;
}

// ---------------- K4: M via tf32 MMA: M[b,l*4+q,o] = A(lxh) @ linw(q) -----
// block tile 128(l) x 128(n of 1024 wide (q,o)), K-chunk 32, 8 warps
__global__ __launch_bounds__(256) void k_mgemm2(const float* __restrict__ ph,
                                                const float* __restrict__ linw) {
    int b = blockIdx.z;
    int n0 = blockIdx.x * 128;   // 0..896 ; q = n0>>8, o0 = n0&255
    int l0 = blockIdx.y * 128;
    int q = n0 >> 8;
    int o0 = n0 & 255;
    __shared__ __align__(16) float As[32][136];  // [k][l]
    __shared__ __align__(16) float Bs[32][136];  // [k][n]

    int tid = threadIdx.x;
    int wid = tid >> 5, lane = tid & 31;
    int warpRow = wid >> 1, warpCol = wid & 1;
    int g = lane >> 2, tg = lane & 3;

    const float* Ab = ph + (size_t)b * ND * NL;      // A[l,h] = Ab[h*NL + l]
    const float* Bb = linw + (size_t)q * 256 * 256;  // B[h,o] = Bb[h*256+o]

    float acc[2][8][4];
#pragma unroll
    for (int mt = 0; mt < 2; mt++)
#pragma unroll
        for (int nt = 0; nt < 8; nt++)
#pragma unroll
            for (int j = 0; j < 4; j++) acc[mt][nt][j] = 0.0f;

    for (int k0 = 0; k0 < 256; k0 += 32) {
        __syncthreads();
#pragma unroll
        for (int i = 0; i < 4; i++) {
            int idx = i * 256 + tid;
            int r = idx >> 5, c4 = (idx & 31) * 4;
            float4 av = *(const float4*)(Ab + (size_t)(k0 + r) * NL + l0 + c4);
            As[r][c4 + 0] = to_tf32(av.x);
            As[r][c4 + 1] = to_tf32(av.y);
            As[r][c4 + 2] = to_tf32(av.z);
            As[r][c4 + 3] = to_tf32(av.w);
        }
#pragma unroll
        for (int i = 0; i < 4; i++) {
            int idx = i * 256 + tid;
            int r = idx >> 5, c4 = (idx & 31) * 4;
            float4 bv = *(const float4*)(Bb + (size_t)(k0 + r) * 256 + o0 + c4);
            Bs[r][c4 + 0] = to_tf32(bv.x);
            Bs[r][c4 + 1] = to_tf32(bv.y);
            Bs[r][c4 + 2] = to_tf32(bv.z);
            Bs[r][c4 + 3] = to_tf32(bv.w);
        }
        __syncthreads();
#pragma unroll
        for (int ks = 0; ks < 4; ks++) {
            int k = ks * 8;
            uint32_t af[2][4];
#pragma unroll
            for (int mt = 0; mt < 2; mt++) {
                int r0 = warpRow * 32 + mt * 16 + g;
                af[mt][0] = __float_as_uint(As[k + tg][r0]);
                af[mt][1] = __float_as_uint(As[k + tg][r0 + 8]);
                af[mt][2] = __float_as_uint(As[k + tg + 4][r0]);
                af[mt][3] = __float_as_uint(As[k + tg + 4][r0 + 8]);
            }
#pragma unroll
            for (int nt = 0; nt < 8; nt++) {
                int col = warpCol * 64 + nt * 8 + g;
                uint32_t b0 = __float_as_uint(Bs[k + tg][col]);
                uint32_t b1 = __float_as_uint(Bs[k + tg + 4][col]);
                mma_tf32(acc[0][nt], af[0][0], af[0][1], af[0][2], af[0][3], b0, b1);
                mma_tf32(acc[1][nt], af[1][0], af[1][1], af[1][2], af[1][3], b0, b1);
            }
        }
    }
    float* Mb = g_M + (size_t)b * 1024 * 256;
#pragma unroll
    for (int mt = 0; mt < 2; mt++) {
        int lr0 = warpRow * 32 + mt * 16 + g;
        int lr1 = lr0 + 8;
        int row0 = (l0 + lr0) * 4 + q;
        int row1 = (l0 + lr1) * 4 + q;
#pragma unroll
        for (int nt = 0; nt < 8; nt++) {
            int nl = warpCol * 64 + nt * 8 + 2 * tg;
            *(float2*)(Mb + (size_t)row0 * 256 + o0 + nl) =
                make_float2(to_tf32(acc[mt][nt][0]), to_tf32(acc[mt][nt][1]));
            *(float2*)(Mb + (size_t)row1 * 256 + o0 + nl) =
                make_float2(to_tf32(acc[mt][nt][2]), to_tf32(acc[mt][nt][3]));
        }
    }
}

// ---------------- K5: warp-per-t softmax w + wc8 --------------------------
__global__ __launch_bounds__(256) void k_wsm2(const float* __restrict__ mwW,
                                              const float* __restrict__ mcW) {
    int b = blockIdx.y;
    int wid = threadIdx.x >> 5, lane = threadIdx.x & 31;
    int t = blockIdx.x * 8 + wid;
    float* wout = g_w + ((size_t)(b * NT + t)) * 1024;
    if (t >= g_flen[b]) {
#pragma unroll
        for (int j = 0; j < 8; j++)
            *(float4*)(wout + (j * 32 + lane) * 4) = make_float4(0, 0, 0, 0);
        if (lane == 0) {
#pragma unroll
            for (int j = 0; j < 8; j++) g_wc8[((size_t)(b * NT + t)) * 8 + j] = 0.0f;
        }
        return;
    }
    float W0[4] = {__ldg(mwW + 0), __ldg(mwW + 1), __ldg(mwW + 2), __ldg(mwW + 3)};
    float Wc0[2] = {__ldg(mcW + 0), __ldg(mcW + 1)};
    float tf = (float)t;
    const unsigned FULL = 0xffffffffu;

    float lg[8][4];
    float mx[4] = {-1e30f, -1e30f, -1e30f, -1e30f};
    float padv[8];
#pragma unroll
    for (int j = 0; j < 8; j++) {
        int l = j * 32 + lane;
        float4 bz = *(const float4*)(g_bzw + (b * NL + l) * 4);
        float pv = g_pad[b * NL + l];
        padv[j] = pv;
        float bza[4] = {bz.x, bz.y, bz.z, bz.w};
#pragma unroll
        for (int q = 0; q < 4; q++) {
            float z = bza[q] + tf * W0[q];
            float s = swish_fast(z);
            lg[j][q] = (pv != 0.0f) ? -1e30f : s;
            mx[q] = fmaxf(mx[q], lg[j][q]);
        }
    }
#pragma unroll
    for (int off = 16; off > 0; off >>= 1)
#pragma unroll
        for (int q = 0; q < 4; q++)
            mx[q] = fmaxf(mx[q], __shfl_xor_sync(FULL, mx[q], off));

    float sm[4] = {0, 0, 0, 0};
#pragma unroll
    for (int j = 0; j < 8; j++)
#pragma unroll
        for (int q = 0; q < 4; q++) {
            float e = __expf(lg[j][q] - mx[q]);
            lg[j][q] = e;
            sm[q] += e;
        }
#pragma unroll
    for (int off = 16; off > 0; off >>= 1)
#pragma unroll
        for (int q = 0; q < 4; q++)
            sm[q] += __shfl_xor_sync(FULL, sm[q], off);
    float rq[4];
#pragma unroll
    for (int q = 0; q < 4; q++) rq[q] = __fdividef(1.0f, sm[q]);

    float prod[8] = {0, 0, 0, 0, 0, 0, 0, 0};
#pragma unroll
    for (int j = 0; j < 8; j++) {
        int l = j * 32 + lane;
        float wq[4];
#pragma unroll
        for (int q = 0; q < 4; q++) wq[q] = lg[j][q] * rq[q];
        *(float4*)(wout + l * 4) = make_float4(to_tf32(wq[0]), to_tf32(wq[1]),
                                               to_tf32(wq[2]), to_tf32(wq[3]));
        float2 bc = *(const float2*)(g_bzc + (b * NL + l) * 2);
        float cp0 = swish_fast(bc.x + tf * Wc0[0]);
        float cp1 = swish_fast(bc.y + tf * Wc0[1]);
#pragma unroll
        for (int q = 0; q < 4; q++) {
            prod[q * 2 + 0] += wq[q] * cp0;
            prod[q * 2 + 1] += wq[q] * cp1;
        }
    }
#pragma unroll
    for (int off = 16; off > 0; off >>= 1)
#pragma unroll
        for (int j = 0; j < 8; j++) prod[j] += __shfl_xor_sync(FULL, prod[j], off);
    if (lane == 0) {
#pragma unroll
        for (int j = 0; j < 8; j++)
            g_wc8[((size_t)(b * NT + t)) * 8 + j] = prod[j];
    }
}

// ---------------- K6: out = w @ M (tf32 mma) + (wc8 @ lin_c_W) + biases ---
__global__ __launch_bounds__(256) void k_final(
        const float* __restrict__ lwb, const float* __restrict__ lcW,
        const float* __restrict__ lcb, float* __restrict__ out) {
    int b = blockIdx.z;
    int t0 = blockIdx.y * 128;
    int n0 = blockIdx.x * 128;
    __shared__ __align__(16) float As[128][36];
    __shared__ __align__(16) float Bs[32][136];
    __shared__ float sB[128];
    __shared__ float sC[8][128];
    __shared__ float sWC[128][8];

    int tid = threadIdx.x;
    int wid = tid >> 5, lane = tid & 31;
    int warpRow = wid >> 1, warpCol = wid & 1;
    int g = lane >> 2, tg = lane & 3;

    if (tid < 128) sB[tid] = lwb[n0 + tid] + lcb[n0 + tid];
    for (int i = tid; i < 8 * 128; i += 256)
        sC[i >> 7][i & 127] = lcW[(i >> 7) * 256 + n0 + (i & 127)];
    {
        const float* wcb = g_wc8 + (size_t)b * NT * 8;
#pragma unroll
        for (int i = 0; i < 4; i++) {
            int idx = i * 256 + tid;
            int r = idx >> 3;
            float v = (t0 + r < NT) ? wcb[(size_t)(t0 + r) * 8 + (idx & 7)] : 0.0f;
            sWC[r][idx & 7] = v;
        }
    }

    const float* Ab = g_w + (size_t)b * NT * 1024;
    const float* Bb = g_M + (size_t)b * 1024 * 256;

    float acc[2][8][4];
#pragma unroll
    for (int mt = 0; mt < 2; mt++)
#pragma unroll
        for (int nt = 0; nt < 8; nt++)
#pragma unroll
            for (int j = 0; j < 4; j++) acc[mt][nt][j] = 0.0f;

    for (int k0 = 0; k0 < 1024; k0 += 32) {
        __syncthreads();
#pragma unroll
        for (int i = 0; i < 4; i++) {
            int idx = i * 256 + tid;
            int r = idx >> 3, c4 = (idx & 7) * 4;
            float4 av = (t0 + r < NT)
                ? *(const float4*)(Ab + (size_t)(t0 + r) * 1024 + k0 + c4)
                : make_float4(0, 0, 0, 0);
            *(float4*)(&As[r][c4]) = av;
        }
#pragma unroll
        for (int i = 0; i < 4; i++) {
            int idx = i * 256 + tid;
            int r = idx >> 5, c4 = (idx & 31) * 4;
            float4 bv = *(const float4*)(Bb + (size_t)(k0 + r) * 256 + n0 + c4);
            *(float4*)(&Bs[r][c4]) = bv;
        }
        __syncthreads();
#pragma unroll
        for (int ks = 0; ks < 4; ks++) {
            int k = ks * 8;
            uint32_t af[2][4];
#pragma unroll
            for (int mt = 0; mt < 2; mt++) {
                int r0 = warpRow * 32 + mt * 16 + g;
                af[mt][0] = __float_as_uint(As[r0][k + tg]);
                af[mt][1] = __float_as_uint(As[r0 + 8][k + tg]);
                af[mt][2] = __float_as_uint(As[r0][k + tg + 4]);
                af[mt][3] = __float_as_uint(As[r0 + 8][k + tg + 4]);
            }
#pragma unroll
            for (int nt = 0; nt < 8; nt++) {
                int col = warpCol * 64 + nt * 8 + g;
                uint32_t b0 = __float_as_uint(Bs[k + tg][col]);
                uint32_t b1 = __float_as_uint(Bs[k + tg + 4][col]);
                mma_tf32(acc[0][nt], af[0][0], af[0][1], af[0][2], af[0][3], b0, b1);
                mma_tf32(acc[1][nt], af[1][0], af[1][1], af[1][2], af[1][3], b0, b1);
            }
        }
    }

#pragma unroll
    for (int mt = 0; mt < 2; mt++) {
        int lr0 = warpRow * 32 + mt * 16 + g;
        int lr1 = lr0 + 8;
        float wc0[8], wc1[8];
#pragma unroll
        for (int j = 0; j < 8; j++) { wc0[j] = sWC[lr0][j]; wc1[j] = sWC[lr1][j]; }
        int T0 = t0 + lr0, T1 = t0 + lr1;
#pragma unroll
        for (int nt = 0; nt < 8; nt++) {
            int nl = warpCol * 64 + nt * 8 + 2 * tg;
            float bias0 = sB[nl], bias1 = sB[nl + 1];
            float e00 = acc[mt][nt][0] + bias0, e01 = acc[mt][nt][1] + bias1;
            float e10 = acc[mt][nt][2] + bias0, e11 = acc[mt][nt][3] + bias1;
#pragma unroll
            for (int j = 0; j < 8; j++) {
                float c0v = sC[j][nl], c1v = sC[j][nl + 1];
                e00 += wc0[j] * c0v; e01 += wc0[j] * c1v;
                e10 += wc1[j] * c0v; e11 += wc1[j] * c1v;
            }
            if (T0 < NT)
                *(float2*)(out + ((size_t)(b * NT + T0)) * 256 + n0 + nl) = make_float2(e00, e01);
            if (T1 < NT)
                *(float2*)(out + ((size_t)(b * NT + T1)) * 256 + n0 + nl) = make_float2(e10, e11);
        }
    }
}

// ---------------------------------------------------------------------------
extern "C" void kernel_launch(void* const* d_in, const int* in_sizes, int n_in,
                              void* d_out, int out_size) {
    const float* durations = (const float*)d_in[0];
    const float* phoneme   = (const float*)d_in[1];
    // d_in[2] = phoneme_mask (unused; derived from durations == 0)
    const float* proj_w_W  = (const float*)d_in[3];
    const float* proj_w_b  = (const float*)d_in[4];
    const float* conv_w_W  = (const float*)d_in[5];
    const float* conv_w_b  = (const float*)d_in[6];
    const float* mlp_w_W   = (const float*)d_in[7];
    const float* mlp_w_b   = (const float*)d_in[8];
    const float* lin_w_W   = (const float*)d_in[9];
    const float* lin_w_b   = (const float*)d_in[10];
    const float* proj_c_W  = (const float*)d_in[11];
    const float* proj_c_b  = (const float*)d_in[12];
    const float* conv_c_W  = (const float*)d_in[13];
    const float* conv_c_b  = (const float*)d_in[14];
    const float* mlp_c_W   = (const float*)d_in[15];
    const float* mlp_c_b   = (const float*)d_in[16];
    const float* lin_c_W   = (const float*)d_in[17];
    const float* lin_c_b   = (const float*)d_in[18];
    float* out = (float*)d_out;

    k_scan<<<NB, NL>>>(durations);
    k_weff<<<dim3(3, 8, 2), ND>>>(proj_w_W, conv_w_W, proj_c_W, conv_c_W);
    k_cwpb<<<1, 64>>>(conv_w_W, proj_w_b, conv_c_W, proj_c_b);
    k_conv_part<<<dim3(NB, 16), NL>>>(phoneme);
    k_conv_fin<<<NB, NL>>>(durations, conv_w_b, conv_c_b,
                           mlp_w_W, mlp_w_b, mlp_c_W, mlp_c_b);
    k_mgemm2<<<dim3(8, 2, NB), 256>>>(phoneme, lin_w_W);
    k_wsm2<<<dim3(125, NB), 256>>>(mlp_w_W, mlp_c_W);
    k_final<<<dim3(2, 8, NB), 256>>>(lin_w_b, lin_c_W, lin_c_b, out);
}

// round 7
// speedup vs baseline: 3.7225x; 1.2704x over previous
#include <cuda_runtime.h>
#include <cuda_bf16.h>
#include <math.h>
#include <stdint.h>

#define NB 16
#define ND 256
#define NL 256
#define NT 1000
#define NCH 8
#define NDW 4
#define NDC 2

// ---------------- scratch (device globals; no allocations allowed) ----------
__device__ __align__(16) float g_sd[NB * NL];
__device__ __align__(16) float g_sk[NB * NL];
__device__ int g_flen[NB];
__device__ __align__(16) float g_weff[ND * 48];       // [d][br*8+ch][k]
__device__ __align__(16) float g_cwpb[48];            // [br][ch][k]
__device__ __align__(16) float g_hpart[32 * NB * NL * 16]; // [chunk][(b*L+l)*16+idx]
__device__ __align__(16) float g_bzw[NB * NL * 4];    // t-invariant w-logit base
__device__ __align__(16) float g_bzc[NB * NL * 2];    // t-invariant c base
__device__ __align__(16) float g_pad[NB * NL];        // 1.0 if phone_pad
__device__ __align__(16) float g_M[(size_t)NB * 1024 * 256];   // [b][l*4+q][o]  (tf32)

__device__ __forceinline__ float swishf(float z) {
    return z / (1.0f + expf(-z));
}
__device__ __forceinline__ float swish_fast(float z) {
    return __fdividef(z, 1.0f + __expf(-z));
}
__device__ __forceinline__ float to_tf32(float x) {
    uint32_t u;
    asm("cvt.rna.tf32.f32 %0, %1;" : "=r"(u) : "f"(x));
    return __uint_as_float(u);
}
__device__ __forceinline__ void mma_tf32(float c[4], uint32_t a0, uint32_t a1,
                                         uint32_t a2, uint32_t a3,
                                         uint32_t b0, uint32_t b1) {
    asm volatile(
        "mma.sync.aligned.m16n8k8.row.col.f32.tf32.tf32.f32 "
        "{%0,%1,%2,%3}, {%4,%5,%6,%7}, {%8,%9}, {%0,%1,%2,%3};\n"
        : "+f"(c[0]), "+f"(c[1]), "+f"(c[2]), "+f"(c[3])
        : "r"(a0), "r"(a1), "r"(a2), "r"(a3), "r"(b0), "r"(b1));
}

// ---------------- K1: cumsum scan, frame_len ------------------------------
__global__ void k_scan(const float* __restrict__ dur) {
    int b = blockIdx.x, l = threadIdx.x;
    __shared__ float s[NL];
    float x = dur[b * NL + l];
    s[l] = x;
    __syncthreads();
#pragma unroll
    for (int off = 1; off < NL; off <<= 1) {
        float v = (l >= off) ? s[l - off] : 0.0f;
        __syncthreads();
        s[l] += v;
        __syncthreads();
    }
    float sd = s[l];
    g_sd[b * NL + l] = sd;
    g_sk[b * NL + l] = sd - x;
    if (l == 0) {
        float tot = s[NL - 1];
        int fl = (int)rintf(tot);
        if (fl < 0) fl = 0;
        if (fl > NT) fl = NT;
        g_flen[b] = fl;
    }
}

// ---------------- K2: fold projection into conv weights -------------------
__global__ void k_weff(const float* __restrict__ pwW, const float* __restrict__ cwW,
                       const float* __restrict__ pcW, const float* __restrict__ ccW) {
    int k = blockIdx.x, ch = blockIdx.y, br = blockIdx.z, d = threadIdx.x;
    const float* cw = br ? ccW : cwW;
    const float* pw = br ? pcW : pwW;
    float acc = 0.0f;
#pragma unroll 4
    for (int o = 0; o < ND; o++)
        acc += cw[(ch * ND + o) * 3 + k] * pw[o * ND + d];
    g_weff[d * 48 + (br * 8 + ch) * 3 + k] = acc;
}

__global__ void k_cwpb(const float* __restrict__ cwW, const float* __restrict__ pwb,
                       const float* __restrict__ ccW, const float* __restrict__ pcb) {
    int i = threadIdx.x;
    if (i >= 48) return;
    int br = i / 24, rem = i % 24, ch = rem / 3, k = rem % 3;
    const float* cw = br ? ccW : cwW;
    const float* pb = br ? pcb : pwb;
    float a = 0.0f;
    for (int o = 0; o < ND; o++) a += cw[(ch * ND + o) * 3 + k] * pb[o];
    g_cwpb[i] = a;
}

// ---------------- K3a: partial conv over 8-d chunks -----------------------
__global__ void k_conv_part(const float* __restrict__ ph) {
    int b = blockIdx.x, c = blockIdx.y, l = threadIdx.x;
    __shared__ __align__(16) float sWe[8 * 48];
    for (int i = l; i < 8 * 48; i += NL) sWe[i] = g_weff[c * 8 * 48 + i];
    __syncthreads();

    const float* phb = ph + (size_t)b * ND * NL + (size_t)(c * 8) * NL;
    float acc[16];
#pragma unroll
    for (int i = 0; i < 16; i++) acc[i] = 0.0f;

#pragma unroll
    for (int dd = 0; dd < 8; dd++) {
        float vm = (l > 0) ? phb[dd * NL + l - 1] : 0.0f;
        float v0 = phb[dd * NL + l];
        float vp = (l < NL - 1) ? phb[dd * NL + l + 1] : 0.0f;
        float v[3] = {vm, v0, vp};
        const float* wd = sWe + dd * 48;
#pragma unroll
        for (int lin = 0; lin < 48; lin += 4) {
            float4 w = *(const float4*)(wd + lin);
            acc[(lin + 0) / 3] += w.x * v[(lin + 0) % 3];
            acc[(lin + 1) / 3] += w.y * v[(lin + 1) % 3];
            acc[(lin + 2) / 3] += w.z * v[(lin + 2) % 3];
            acc[(lin + 3) / 3] += w.w * v[(lin + 3) % 3];
        }
    }
    float* outp = g_hpart + ((size_t)(c * NB + b) * NL + l) * 16;
#pragma unroll
    for (int i = 0; i < 16; i += 4)
        *(float4*)(outp + i) = make_float4(acc[i], acc[i + 1], acc[i + 2], acc[i + 3]);
}

// ---- K3b: reduce partials + bias + swish, fold h into t-invariant bases --
__global__ void k_conv_fin(const float* __restrict__ dur,
                           const float* __restrict__ cwb, const float* __restrict__ ccb,
                           const float* __restrict__ mwW, const float* __restrict__ mwb,
                           const float* __restrict__ mcW, const float* __restrict__ mcb) {
    int b = blockIdx.x, l = threadIdx.x;
    __shared__ float smw[40], smwb[4], smc[20], smcb[2];
    if (l < 40) smw[l] = mwW[l];
    if (l < 4) smwb[l] = mwb[l];
    if (l >= 64 && l < 84) smc[l - 64] = mcW[l - 64];
    if (l >= 96 && l < 98) smcb[l - 96] = mcb[l - 96];

    float acc[16];
#pragma unroll
    for (int i = 0; i < 16; i++) acc[i] = 0.0f;
#pragma unroll
    for (int c = 0; c < 32; c++) {
        const float* p = g_hpart + ((size_t)(c * NB + b) * NL + l) * 16;
#pragma unroll
        for (int i = 0; i < 16; i += 4) {
            float4 v = *(const float4*)(p + i);
            acc[i] += v.x; acc[i + 1] += v.y; acc[i + 2] += v.z; acc[i + 3] += v.w;
        }
    }
    float h[16];
#pragma unroll
    for (int idx = 0; idx < 16; idx++) {
        int br = idx >> 3, ch = idx & 7;
        float bias = (br ? ccb : cwb)[ch];
        float c0 = g_cwpb[br * 24 + ch * 3 + 0];
        float c1 = g_cwpb[br * 24 + ch * 3 + 1];
        float c2 = g_cwpb[br * 24 + ch * 3 + 2];
        bias += c0 + c1 + c2;
        if (l == 0) bias -= c0;
        if (l == NL - 1) bias -= c2;
        h[idx] = swishf(acc[idx] + bias);
    }
    __syncthreads();

    bool pad = (dur[b * NL + l] == 0.0f);
    float skv = g_sk[b * NL + l];
    float sdv = g_sd[b * NL + l];
    float E = pad ? 0.0f : (sdv - skv);
    float oms = pad ? 0.0f : (1.0f - skv);   // (t+1-sk) = t + oms
    float bzw[4];
#pragma unroll
    for (int q = 0; q < 4; q++) {
        float z = smwb[q] + oms * smw[q] + E * smw[4 + q];
#pragma unroll
        for (int ch = 0; ch < 8; ch++) z += (pad ? 0.0f : h[ch]) * smw[(2 + ch) * 4 + q];
        bzw[q] = z;
    }
    *(float4*)(g_bzw + (b * NL + l) * 4) = make_float4(bzw[0], bzw[1], bzw[2], bzw[3]);
    float bzc[2];
#pragma unroll
    for (int p = 0; p < 2; p++) {
        float z = smcb[p] + oms * smc[p] + E * smc[2 + p];
#pragma unroll
        for (int ch = 0; ch < 8; ch++) z += (pad ? 0.0f : h[8 + ch]) * smc[(2 + ch) * 2 + p];
        bzc[p] = z;
    }
    *(float2*)(g_bzc + (b * NL + l) * 2) = make_float2(bzc[0], bzc[1]);
    g_pad[b * NL + l] = pad ? 1.0f : 0.0f;
}

// ---------------- K4: M via tf32 MMA --------------------------------------
__global__ __launch_bounds__(256) void k_mgemm2(const float* __restrict__ ph,
                                                const float* __restrict__ linw) {
    int b = blockIdx.z;
    int n0 = blockIdx.x * 128;
    int l0 = blockIdx.y * 128;
    int q = n0 >> 8;
    int o0 = n0 & 255;
    __shared__ __align__(16) float As[32][136];  // [k][l]
    __shared__ __align__(16) float Bs[32][136];  // [k][n]

    int tid = threadIdx.x;
    int wid = tid >> 5, lane = tid & 31;
    int warpRow = wid >> 1, warpCol = wid & 1;
    int g = lane >> 2, tg = lane & 3;

    const float* Ab = ph + (size_t)b * ND * NL;
    const float* Bb = linw + (size_t)q * 256 * 256;

    float acc[2][8][4];
#pragma unroll
    for (int mt = 0; mt < 2; mt++)
#pragma unroll
        for (int nt = 0; nt < 8; nt++)
#pragma unroll
            for (int j = 0; j < 4; j++) acc[mt][nt][j] = 0.0f;

    for (int k0 = 0; k0 < 256; k0 += 32) {
        __syncthreads();
#pragma unroll
        for (int i = 0; i < 4; i++) {
            int idx = i * 256 + tid;
            int r = idx >> 5, c4 = (idx & 31) * 4;
            float4 av = *(const float4*)(Ab + (size_t)(k0 + r) * NL + l0 + c4);
            As[r][c4 + 0] = to_tf32(av.x);
            As[r][c4 + 1] = to_tf32(av.y);
            As[r][c4 + 2] = to_tf32(av.z);
            As[r][c4 + 3] = to_tf32(av.w);
        }
#pragma unroll
        for (int i = 0; i < 4; i++) {
            int idx = i * 256 + tid;
            int r = idx >> 5, c4 = (idx & 31) * 4;
            float4 bv = *(const float4*)(Bb + (size_t)(k0 + r) * 256 + o0 + c4);
            Bs[r][c4 + 0] = to_tf32(bv.x);
            Bs[r][c4 + 1] = to_tf32(bv.y);
            Bs[r][c4 + 2] = to_tf32(bv.z);
            Bs[r][c4 + 3] = to_tf32(bv.w);
        }
        __syncthreads();
#pragma unroll
        for (int ks = 0; ks < 4; ks++) {
            int k = ks * 8;
            uint32_t af[2][4];
#pragma unroll
            for (int mt = 0; mt < 2; mt++) {
                int r0 = warpRow * 32 + mt * 16 + g;
                af[mt][0] = __float_as_uint(As[k + tg][r0]);
                af[mt][1] = __float_as_uint(As[k + tg][r0 + 8]);
                af[mt][2] = __float_as_uint(As[k + tg + 4][r0]);
                af[mt][3] = __float_as_uint(As[k + tg + 4][r0 + 8]);
            }
#pragma unroll
            for (int nt = 0; nt < 8; nt++) {
                int col = warpCol * 64 + nt * 8 + g;
                uint32_t b0 = __float_as_uint(Bs[k + tg][col]);
                uint32_t b1 = __float_as_uint(Bs[k + tg + 4][col]);
                mma_tf32(acc[0][nt], af[0][0], af[0][1], af[0][2], af[0][3], b0, b1);
                mma_tf32(acc[1][nt], af[1][0], af[1][1], af[1][2], af[1][3], b0, b1);
            }
        }
    }
    float* Mb = g_M + (size_t)b * 1024 * 256;
#pragma unroll
    for (int mt = 0; mt < 2; mt++) {
        int lr0 = warpRow * 32 + mt * 16 + g;
        int lr1 = lr0 + 8;
        int row0 = (l0 + lr0) * 4 + q;
        int row1 = (l0 + lr1) * 4 + q;
#pragma unroll
        for (int nt = 0; nt < 8; nt++) {
            int nl = warpCol * 64 + nt * 8 + 2 * tg;
            *(float2*)(Mb + (size_t)row0 * 256 + o0 + nl) =
                make_float2(to_tf32(acc[mt][nt][0]), to_tf32(acc[mt][nt][1]));
            *(float2*)(Mb + (size_t)row1 * 256 + o0 + nl) =
                make_float2(to_tf32(acc[mt][nt][2]), to_tf32(acc[mt][nt][3]));
        }
    }
}

// ---------------- K6: fused softmax-w + tf32 GEMM + wc epilogue -----------
// grid (1, 8, NB), 512 threads, BM=128 t-rows, BN=256, K=1024 (l*4+q)
#define SM_AS    0                  // 128*36   = 4608 floats
#define SM_BS    4608               // 32*264   = 8448
#define SM_SC    13056              // 8*256    = 2048
#define SM_SB    15104              // 256
#define SM_SWC   15360              // 128*8    = 1024
#define SM_MX    16384              // 128*4    = 512
#define SM_RS    16896              // 128*4    = 512
#define SM_TOTF  17408

__global__ __launch_bounds__(512) void k_final2(
        const float* __restrict__ lwb, const float* __restrict__ lcW,
        const float* __restrict__ lcb, const float* __restrict__ mwW,
        const float* __restrict__ mcW, float* __restrict__ out) {
    extern __shared__ float sm[];
    float (*As)[36]  = (float(*)[36])(sm + SM_AS);
    float (*Bs)[264] = (float(*)[264])(sm + SM_BS);
    float (*sC)[256] = (float(*)[256])(sm + SM_SC);
    float* sB   = sm + SM_SB;
    float (*sWC)[8] = (float(*)[8])(sm + SM_SWC);
    float (*smx)[4] = (float(*)[4])(sm + SM_MX);
    float (*srs)[4] = (float(*)[4])(sm + SM_RS);

    int b = blockIdx.z;
    int t0 = blockIdx.y * 128;
    int tid = threadIdx.x;
    int wid = tid >> 5, lane = tid & 31;
    int warpRow = wid >> 2, warpCol = wid & 3;
    int g = lane >> 2, tg = lane & 3;

    float W0[4] = {__ldg(mwW + 0), __ldg(mwW + 1), __ldg(mwW + 2), __ldg(mwW + 3)};
    float Wc0[2] = {__ldg(mcW + 0), __ldg(mcW + 1)};
    int flen = g_flen[b];
    const float* bzwb = g_bzw + b * NL * 4;
    const float* bzcb = g_bzc + b * NL * 2;
    const float* padb = g_pad + b * NL;
    const unsigned FULL = 0xffffffffu;

    // epilogue constants
    if (tid < 256) sB[tid] = lwb[tid] + lcb[tid];
    for (int i = tid; i < 8 * 256; i += 512)
        sC[i >> 8][i & 255] = lcW[i];

    // ---- prepass: per-row softmax stats + wc8 (warp wid owns rows 8w..8w+7)
#pragma unroll 1
    for (int rr = 0; rr < 8; rr++) {
        int r = wid * 8 + rr;
        int t = t0 + r;
        float tf = (float)t;
        if (t >= flen) {
            if (lane == 0) {
#pragma unroll
                for (int q = 0; q < 4; q++) { smx[r][q] = 0.0f; srs[r][q] = 0.0f; }
#pragma unroll
                for (int j = 0; j < 8; j++) sWC[r][j] = 0.0f;
            }
            continue;
        }
        float lg[8][4];
        float mx[4] = {-1e30f, -1e30f, -1e30f, -1e30f};
#pragma unroll
        for (int j = 0; j < 8; j++) {
            int l = j * 32 + lane;
            float4 bz = *(const float4*)(bzwb + l * 4);
            float pv = padb[l];
            float bza[4] = {bz.x, bz.y, bz.z, bz.w};
#pragma unroll
            for (int q = 0; q < 4; q++) {
                float s = swish_fast(bza[q] + tf * W0[q]);
                lg[j][q] = (pv != 0.0f) ? -1e30f : s;
                mx[q] = fmaxf(mx[q], lg[j][q]);
            }
        }
#pragma unroll
        for (int off = 16; off > 0; off >>= 1)
#pragma unroll
            for (int q = 0; q < 4; q++)
                mx[q] = fmaxf(mx[q], __shfl_xor_sync(FULL, mx[q], off));
        float smv[4] = {0, 0, 0, 0};
#pragma unroll
        for (int j = 0; j < 8; j++)
#pragma unroll
            for (int q = 0; q < 4; q++) {
                float e = __expf(lg[j][q] - mx[q]);
                lg[j][q] = e;
                smv[q] += e;
            }
#pragma unroll
        for (int off = 16; off > 0; off >>= 1)
#pragma unroll
            for (int q = 0; q < 4; q++)
                smv[q] += __shfl_xor_sync(FULL, smv[q], off);
        float rs[4];
#pragma unroll
        for (int q = 0; q < 4; q++) rs[q] = __fdividef(1.0f, smv[q]);

        float wc[8] = {0, 0, 0, 0, 0, 0, 0, 0};
#pragma unroll
        for (int j = 0; j < 8; j++) {
            int l = j * 32 + lane;
            float2 bc = *(const float2*)(bzcb + l * 2);
            float cp0 = swish_fast(bc.x + tf * Wc0[0]);
            float cp1 = swish_fast(bc.y + tf * Wc0[1]);
#pragma unroll
            for (int q = 0; q < 4; q++) {
                float w = lg[j][q] * rs[q];
                wc[q * 2 + 0] += w * cp0;
                wc[q * 2 + 1] += w * cp1;
            }
        }
#pragma unroll
        for (int off = 16; off > 0; off >>= 1)
#pragma unroll
            for (int j = 0; j < 8; j++) wc[j] += __shfl_xor_sync(FULL, wc[j], off);
        if (lane == 0) {
#pragma unroll
            for (int q = 0; q < 4; q++) { smx[r][q] = mx[q]; srs[r][q] = rs[q]; }
#pragma unroll
            for (int j = 0; j < 8; j++) sWC[r][j] = wc[j];
        }
    }
    __syncthreads();

    // per-thread A-row constants (2 slots)
    int rA0 = tid >> 3, rA1 = 64 + (tid >> 3);
    int cA4 = (tid & 7) * 4;
    float tfA0 = (float)(t0 + rA0), tfA1 = (float)(t0 + rA1);
    float mxA0[4], rsA0[4], mxA1[4], rsA1[4];
#pragma unroll
    for (int q = 0; q < 4; q++) {
        mxA0[q] = smx[rA0][q]; rsA0[q] = srs[rA0][q];
        mxA1[q] = smx[rA1][q]; rsA1[q] = srs[rA1][q];
    }

    const float* Bb = g_M + (size_t)b * 1024 * 256;

    float acc[2][8][4];
#pragma unroll
    for (int mt = 0; mt < 2; mt++)
#pragma unroll
        for (int nt = 0; nt < 8; nt++)
#pragma unroll
            for (int j = 0; j < 4; j++) acc[mt][nt][j] = 0.0f;

    for (int k0 = 0; k0 < 1024; k0 += 32) {
        __syncthreads();
        // A tile: compute w on the fly. one float4 covers one l, q=0..3
        {
            int l = (k0 + cA4) >> 2;
            float4 bz = *(const float4*)(bzwb + l * 4);
            float pv = padb[l];
            float bza[4] = {bz.x, bz.y, bz.z, bz.w};
            float w0[4], w1[4];
#pragma unroll
            for (int q = 0; q < 4; q++) {
                float s0 = swish_fast(bza[q] + tfA0 * W0[q]);
                s0 = (pv != 0.0f) ? -1e30f : s0;
                w0[q] = __expf(s0 - mxA0[q]) * rsA0[q];
                float s1 = swish_fast(bza[q] + tfA1 * W0[q]);
                s1 = (pv != 0.0f) ? -1e30f : s1;
                w1[q] = __expf(s1 - mxA1[q]) * rsA1[q];
            }
            *(float4*)(&As[rA0][cA4]) = make_float4(to_tf32(w0[0]), to_tf32(w0[1]),
                                                    to_tf32(w0[2]), to_tf32(w0[3]));
            *(float4*)(&As[rA1][cA4]) = make_float4(to_tf32(w1[0]), to_tf32(w1[1]),
                                                    to_tf32(w1[2]), to_tf32(w1[3]));
        }
        // B tile: 32 x 256
#pragma unroll
        for (int i = 0; i < 4; i++) {
            int idx = i * 512 + tid;
            int r = idx >> 6, c4 = (idx & 63) * 4;
            float4 bv = *(const float4*)(Bb + (size_t)(k0 + r) * 256 + c4);
            *(float4*)(&Bs[r][c4]) = bv;
        }
        __syncthreads();
#pragma unroll
        for (int ks = 0; ks < 4; ks++) {
            int k = ks * 8;
            uint32_t af[2][4];
#pragma unroll
            for (int mt = 0; mt < 2; mt++) {
                int r0 = warpRow * 32 + mt * 16 + g;
                af[mt][0] = __float_as_uint(As[r0][k + tg]);
                af[mt][1] = __float_as_uint(As[r0 + 8][k + tg]);
                af[mt][2] = __float_as_uint(As[r0][k + tg + 4]);
                af[mt][3] = __float_as_uint(As[r0 + 8][k + tg + 4]);
            }
#pragma unroll
            for (int nt = 0; nt < 8; nt++) {
                int col = warpCol * 64 + nt * 8 + g;
                uint32_t b0 = __float_as_uint(Bs[k + tg][col]);
                uint32_t b1 = __float_as_uint(Bs[k + tg + 4][col]);
                mma_tf32(acc[0][nt], af[0][0], af[0][1], af[0][2], af[0][3], b0, b1);
                mma_tf32(acc[1][nt], af[1][0], af[1][1], af[1][2], af[1][3], b0, b1);
            }
        }
    }

    // epilogue
#pragma unroll
    for (int mt = 0; mt < 2; mt++) {
        int lr0 = warpRow * 32 + mt * 16 + g;
        int lr1 = lr0 + 8;
        float wc0[8], wc1[8];
#pragma unroll
        for (int j = 0; j < 8; j++) { wc0[j] = sWC[lr0][j]; wc1[j] = sWC[lr1][j]; }
        int T0 = t0 + lr0, T1 = t0 + lr1;
#pragma unroll
        for (int nt = 0; nt < 8; nt++) {
            int nl = warpCol * 64 + nt * 8 + 2 * tg;
            float bias0 = sB[nl], bias1 = sB[nl + 1];
            float e00 = acc[mt][nt][0] + bias0, e01 = acc[mt][nt][1] + bias1;
            float e10 = acc[mt][nt][2] + bias0, e11 = acc[mt][nt][3] + bias1;
#pragma unroll
            for (int j = 0; j < 8; j++) {
                float c0v = sC[j][nl], c1v = sC[j][nl + 1];
                e00 += wc0[j] * c0v; e01 += wc0[j] * c1v;
                e10 += wc1[j] * c0v; e11 += wc1[j] * c1v;
            }
            if (T0 < NT)
                *(float2*)(out + ((size_t)(b * NT + T0)) * 256 + nl) = make_float2(e00, e01);
            if (T1 < NT)
                *(float2*)(out + ((size_t)(b * NT + T1)) * 256 + nl) = make_float2(e10, e11);
        }
    }
}

// ---------------------------------------------------------------------------
extern "C" void kernel_launch(void* const* d_in, const int* in_sizes, int n_in,
                              void* d_out, int out_size) {
    const float* durations = (const float*)d_in[0];
    const float* phoneme   = (const float*)d_in[1];
    // d_in[2] = phoneme_mask (unused; derived from durations == 0)
    const float* proj_w_W  = (const float*)d_in[3];
    const float* proj_w_b  = (const float*)d_in[4];
    const float* conv_w_W  = (const float*)d_in[5];
    const float* conv_w_b  = (const float*)d_in[6];
    const float* mlp_w_W   = (const float*)d_in[7];
    const float* mlp_w_b   = (const float*)d_in[8];
    const float* lin_w_W   = (const float*)d_in[9];
    const float* lin_w_b   = (const float*)d_in[10];
    const float* proj_c_W  = (const float*)d_in[11];
    const float* proj_c_b  = (const float*)d_in[12];
    const float* conv_c_W  = (const float*)d_in[13];
    const float* conv_c_b  = (const float*)d_in[14];
    const float* mlp_c_W   = (const float*)d_in[15];
    const float* mlp_c_b   = (const float*)d_in[16];
    const float* lin_c_W   = (const float*)d_in[17];
    const float* lin_c_b   = (const float*)d_in[18];
    float* out = (float*)d_out;

    static int smset = 0;
    if (!smset) {
        cudaFuncSetAttribute(k_final2, cudaFuncAttributeMaxDynamicSharedMemorySize,
                             SM_TOTF * sizeof(float));
        smset = 1;
    }

    k_scan<<<NB, NL>>>(durations);
    k_weff<<<dim3(3, 8, 2), ND>>>(proj_w_W, conv_w_W, proj_c_W, conv_c_W);
    k_cwpb<<<1, 64>>>(conv_w_W, proj_w_b, conv_c_W, proj_c_b);
    k_conv_part<<<dim3(NB, 32), NL>>>(phoneme);
    k_conv_fin<<<NB, NL>>>(durations, conv_w_b, conv_c_b,
                           mlp_w_W, mlp_w_b, mlp_c_W, mlp_c_b);
    k_mgemm2<<<dim3(8, 2, NB), 256>>>(phoneme, lin_w_W);
    k_final2<<<dim3(1, 8, NB), 512, SM_TOTF * sizeof(float)>>>(
        lin_w_b, lin_c_W, lin_c_b, mlp_w_W, mlp_c_W, out);
}